// round 10
// baseline (speedup 1.0000x reference)
#include <cuda_runtime.h>
#include <cuda_fp16.h>
#include <cstdint>

// Problem constants
#define B_   8
#define TGT  256
#define SRC  256
#define DM   512
#define LDIM 256
#define LOGEPS (-18.420680743952367f)   // log(1e-8)

// -------- scratch (device globals; no allocation) --------
__device__ __half g_dt_h[B_ * TGT * LDIM];   // fp16(dec @ W1)
__device__ __half g_et_h[B_ * SRC * LDIM];   // fp16(enc @ W2)

// ---------------- helpers ----------------
__device__ __forceinline__ unsigned h2tanh(unsigned x) {
    unsigned y;
    asm("tanh.approx.f16x2 %0, %1;" : "=r"(y) : "r"(x));
    return y;
}
__device__ __forceinline__ unsigned h2add(unsigned a, unsigned b) {
    unsigned y;
    asm("add.rn.f16x2 %0, %1, %2;" : "=r"(y) : "r"(a), "r"(b));
    return y;
}
__device__ __forceinline__ unsigned h2fma(unsigned a, unsigned b, unsigned c) {
    unsigned y;
    asm("fma.rn.f16x2 %0, %1, %2, %3;" : "=r"(y) : "r"(a), "r"(b), "r"(c));
    return y;
}
__device__ __forceinline__ float2 h2tof2(unsigned h) {
    float lo, hi;
    asm("{ .reg .b16 l, h;\n\t"
        "  mov.b32 {l, h}, %2;\n\t"
        "  cvt.f32.f16 %0, l;\n\t"
        "  cvt.f32.f16 %1, h; }"
        : "=f"(lo), "=f"(hi) : "r"(h));
    return make_float2(lo, hi);
}
__device__ __forceinline__ void cp_async16(void* smem_dst, const void* gmem_src) {
    unsigned saddr = (unsigned)__cvta_generic_to_shared(smem_dst);
    asm volatile("cp.async.ca.shared.global [%0], [%1], 16;"
                 :: "r"(saddr), "l"(gmem_src));
}
__device__ __forceinline__ void cp_commit() {
    asm volatile("cp.async.commit_group;" ::: "memory");
}
__device__ __forceinline__ void cp_wait0() {
    asm volatile("cp.async.wait_group 0;" ::: "memory");
}
__device__ __forceinline__ void mma16816(float& c0, float& c1, float& c2, float& c3,
                                         unsigned a0, unsigned a1, unsigned a2, unsigned a3,
                                         unsigned b0, unsigned b1) {
    asm volatile(
        "mma.sync.aligned.m16n8k16.row.col.f32.f16.f16.f32 "
        "{%0,%1,%2,%3},{%4,%5,%6,%7},{%8,%9},{%0,%1,%2,%3};"
        : "+f"(c0), "+f"(c1), "+f"(c2), "+f"(c3)
        : "r"(a0), "r"(a1), "r"(a2), "r"(a3), "r"(b0), "r"(b1));
}

// =====================================================================
// Kernel A (HMMA): Yh = fp16(X @ W).  Unchanged from R8 (~9us).
// =====================================================================
#define APADH 40
#define BPADH 34

__global__ __launch_bounds__(256) void gemm_kernel(
    const float* __restrict__ dec, const float* __restrict__ enc,
    const float* __restrict__ W1,  const float* __restrict__ W2)
{
    const float* X; const float* W; __half* Y;
    if (blockIdx.z == 0) { X = dec; W = W1; Y = g_dt_h; }
    else                 { X = enc; W = W2; Y = g_et_h; }

    __shared__ __half Ah[2][128 * APADH];
    __shared__ __half Bt[2][64 * BPADH];   // transposed: [n][k]

    const int tid  = threadIdx.x;
    const int warp = tid >> 5;
    const int lane = tid & 31;
    const int mw   = warp & 3;
    const int nw   = warp >> 2;
    const int g    = lane >> 2;
    const int tig  = lane & 3;

    const int m0 = blockIdx.y * 128;
    const int n0 = blockIdx.x * 64;

    const int ar0 = tid >> 3;
    const int ac4 = tid & 7;
    const int bk0 = tid >> 4;
    const int bn4 = tid & 15;

    float4 ra[4], rb[2];

    auto loadRegs = [&](int kt) {
#pragma unroll
        for (int i = 0; i < 4; i++)
            ra[i] = *(const float4*)(X + (size_t)(m0 + ar0 + 32 * i) * DM
                                       + kt * 32 + ac4 * 4);
#pragma unroll
        for (int i = 0; i < 2; i++)
            rb[i] = *(const float4*)(W + (size_t)(kt * 32 + bk0 + 16 * i) * LDIM
                                       + n0 + bn4 * 4);
    };
    auto storeRegs = [&](int buf) {
#pragma unroll
        for (int i = 0; i < 4; i++) {
            __half2 h0 = __floats2half2_rn(ra[i].x, ra[i].y);
            __half2 h1 = __floats2half2_rn(ra[i].z, ra[i].w);
            uint2 u; u.x = *(unsigned*)&h0; u.y = *(unsigned*)&h1;
            *(uint2*)&Ah[buf][(ar0 + 32 * i) * APADH + ac4 * 4] = u;
        }
#pragma unroll
        for (int i = 0; i < 2; i++) {
            const int kk = bk0 + 16 * i;
            Bt[buf][(bn4 * 4 + 0) * BPADH + kk] = __float2half_rn(rb[i].x);
            Bt[buf][(bn4 * 4 + 1) * BPADH + kk] = __float2half_rn(rb[i].y);
            Bt[buf][(bn4 * 4 + 2) * BPADH + kk] = __float2half_rn(rb[i].z);
            Bt[buf][(bn4 * 4 + 3) * BPADH + kk] = __float2half_rn(rb[i].w);
        }
    };

    float acc[2][4][4];
#pragma unroll
    for (int a = 0; a < 2; a++)
#pragma unroll
        for (int b = 0; b < 4; b++)
#pragma unroll
            for (int c = 0; c < 4; c++) acc[a][b][c] = 0.f;

    loadRegs(0);
    storeRegs(0);
    __syncthreads();

#pragma unroll 1
    for (int kt = 0; kt < 16; kt++) {
        const int buf = kt & 1;
        if (kt < 15) loadRegs(kt + 1);

#pragma unroll
        for (int ks = 0; ks < 2; ks++) {
            const int kb = ks * 16 + 2 * tig;
            unsigned bfr[4][2];
#pragma unroll
            for (int nf = 0; nf < 4; nf++) {
                const __half* bp = &Bt[buf][(nw * 32 + nf * 8 + g) * BPADH + kb];
                bfr[nf][0] = *(const unsigned*)bp;
                bfr[nf][1] = *(const unsigned*)(bp + 8);
            }
#pragma unroll
            for (int mf = 0; mf < 2; mf++) {
                const __half* ap = &Ah[buf][(mw * 32 + mf * 16 + g) * APADH + kb];
                unsigned a0 = *(const unsigned*)ap;
                unsigned a1 = *(const unsigned*)(ap + 8 * APADH);
                unsigned a2 = *(const unsigned*)(ap + 8);
                unsigned a3 = *(const unsigned*)(ap + 8 * APADH + 8);
#pragma unroll
                for (int nf = 0; nf < 4; nf++)
                    mma16816(acc[mf][nf][0], acc[mf][nf][1],
                             acc[mf][nf][2], acc[mf][nf][3],
                             a0, a1, a2, a3, bfr[nf][0], bfr[nf][1]);
            }
        }

        if (kt < 15) {
            storeRegs(buf ^ 1);
            __syncthreads();
        }
    }

#pragma unroll
    for (int mf = 0; mf < 2; mf++) {
#pragma unroll
        for (int nf = 0; nf < 4; nf++) {
            const int row0 = m0 + mw * 32 + mf * 16 + g;
            const int col  = n0 + nw * 32 + nf * 8 + 2 * tig;
            __half2 h01 = __floats2half2_rn(acc[mf][nf][0], acc[mf][nf][1]);
            __half2 h23 = __floats2half2_rn(acc[mf][nf][2], acc[mf][nf][3]);
            *(unsigned*)(Y + (size_t)row0 * LDIM + col)       = *(unsigned*)&h01;
            *(unsigned*)(Y + (size_t)(row0 + 8) * LDIM + col) = *(unsigned*)&h23;
        }
    }
}

// =====================================================================
// Kernel B v4: like R9 (t-tile 2, 1024 blocks, occ 2) but the hot loop
// accumulates with fma.rn.f16x2 — NO cvt, NO f32 FFMA on the XU path.
// f16x2 accumulator dumped to fp32 every 32 l.
// vt kept in smem as half2 pairs.
// smem bytes:
//   sEt  [2][256*72]h  @ 0      73728
//   sDt  [2*256]h      @ 73728   1024
//   sVh  [128]half2    @ 74752    512
//   sSc  [2][257]f     @ 75776   2080 (padded region)
//   sLse [2]f          @ 77856     32
// total 77888 B -> 2 blocks/SM
// =====================================================================
#define EPAD2 72
#define ETILE (256 * EPAD2)
#define OFF2_DT  73728
#define OFF2_VH  74752
#define OFF2_SC  75776
#define OFF2_LSE 77856
#define SMEM_B2_BYTES 77888

__device__ __forceinline__ void load_et_chunk(__half* dst, const __half* src,
                                              int l0, int tid) {
#pragma unroll
    for (int i = 0; i < 4; i++) {
        int idx = tid + i * 512;        // 0..2047: 256 rows x 8 chunks of 8 halves
        int r = idx >> 3, c = idx & 7;
        cp_async16(dst + r * EPAD2 + c * 8, src + r * LDIM + l0 + c * 8);
    }
    cp_commit();
}

__global__ __launch_bounds__(512, 2) void attn_kernel(
    const int* __restrict__ lens, const float* __restrict__ vt,
    float* __restrict__ out)
{
    extern __shared__ char smc[];
    __half*   sEt  = (__half*)smc;
    __half*   sDt  = (__half*)(smc + OFF2_DT);
    unsigned* sVh  = (unsigned*)(smc + OFF2_VH);   // 128 packed half2
    float*    sSc  = (float*)(smc + OFF2_SC);
    float*    sLse = (float*)(smc + OFF2_LSE);

    const int tid = threadIdx.x;
    const int b   = blockIdx.y;
    const int t0  = blockIdx.x * 2;

    const __half* dtH = g_dt_h + ((size_t)b * TGT + t0) * LDIM;  // [2][256]
    const __half* etH = g_et_h + (size_t)b * SRC * LDIM;         // [256][256]

    // prefetch et l-tile 0 (async); dt + vt on sync path
    load_et_chunk(sEt, etH, 0, tid);
    if (tid < 64) {
        *(uint4*)(sDt + tid * 8) = *(const uint4*)(dtH + tid * 8);   // 512 halves
        float4 v = ((const float4*)vt)[tid];
        __half2 h0 = __floats2half2_rn(v.x, v.y);
        __half2 h1 = __floats2half2_rn(v.z, v.w);
        uint2 u; u.x = *(unsigned*)&h0; u.y = *(unsigned*)&h1;
        *(uint2*)&sVh[tid * 2] = u;
    }
    cp_wait0();
    __syncthreads();

    const int w    = tid >> 5;
    const int lane = tid & 31;
    const int r    = w & 1;                 // t-row in pair
    const int s    = (w >> 1) * 32 + lane;  // this lane's source position
    const __half* dR = sDt + r * 256;
    const __half* eRbase = sEt + s * EPAD2;

    float acc = 0.f;

#pragma unroll 1
    for (int st = 0; st < 4; st++) {
        const __half* eR = eRbase + (st & 1) * ETILE;
        if (st < 3)
            load_et_chunk(sEt + ((st + 1) & 1) * ETILE, etH, (st + 1) * 64, tid);

        const int l0 = st * 64;
#pragma unroll
        for (int hh = 0; hh < 2; hh++) {          // two 32-l sub-sweeps
            unsigned acc2 = 0u;                   // f16x2 accumulator
#pragma unroll
            for (int lc = 0; lc < 32; lc += 8) {
                const int le = hh * 32 + lc;      // local l in tile
                const int lg = l0 + le;           // global l
                uint4 e = *(const uint4*)(eR + le);
                uint4 d = *(const uint4*)(dR + lg);        // warp-broadcast
                uint2 v01 = *(const uint2*)&sVh[lg >> 1];
                uint2 v23 = *(const uint2*)&sVh[(lg >> 1) + 2];

                acc2 = h2fma(h2tanh(h2add(d.x, e.x)), v01.x, acc2);
                acc2 = h2fma(h2tanh(h2add(d.y, e.y)), v01.y, acc2);
                acc2 = h2fma(h2tanh(h2add(d.z, e.z)), v23.x, acc2);
                acc2 = h2fma(h2tanh(h2add(d.w, e.w)), v23.y, acc2);
            }
            float2 f = h2tof2(acc2);              // 2 cvt per 32 l (cheap)
            acc += f.x + f.y;
        }

        if (st < 3) cp_wait0();
        __syncthreads();
    }

    // stash raw scores
    sSc[r * 257 + s] = acc;
    __syncthreads();

    // ---- masked log_softmax: warp 0 -> row 0, warp 1 -> row 1 ----
    const int len = lens[b];
    if (w < 2) {
        float v[8];
        float mx = -3.0e38f;
#pragma unroll
        for (int i = 0; i < 8; i++) {
            int ss = lane + 32 * i;
            float x = sSc[w * 257 + ss];
            if (ss >= len) x += LOGEPS;
            v[i] = x;
            mx = fmaxf(mx, x);
        }
#pragma unroll
        for (int o = 16; o > 0; o >>= 1)
            mx = fmaxf(mx, __shfl_xor_sync(0xffffffffu, mx, o));
        float sum = 0.f;
#pragma unroll
        for (int i = 0; i < 8; i++) sum += __expf(v[i] - mx);
#pragma unroll
        for (int o = 16; o > 0; o >>= 1)
            sum += __shfl_xor_sync(0xffffffffu, sum, o);
        if (lane == 0) sLse[w] = mx + __logf(sum);
    }
    __syncthreads();

    // ---- transposed write: out[b][s][t0+lt], 512 threads cover 2x256 ----
    float* outB = out + (size_t)b * SRC * TGT + t0;
    const int lt = tid & 1;
    const int so = tid >> 1;
    float x = sSc[lt * 257 + so];
    if (so >= len) x += LOGEPS;
    outB[(size_t)so * TGT + lt] = x - sLse[lt];
}

// =====================================================================
// launcher
// =====================================================================
extern "C" void kernel_launch(void* const* d_in, const int* in_sizes, int n_in,
                              void* d_out, int out_size)
{
    const float* dec = (const float*)d_in[0];   // [8,256,512]
    const float* enc = (const float*)d_in[1];   // [8,256,512]
    const int*   len = (const int*)  d_in[2];   // [8]
    const float* W1  = (const float*)d_in[3];   // [512,256]
    const float* W2  = (const float*)d_in[4];   // [512,256]
    const float* vt  = (const float*)d_in[5];   // [256]
    float* out = (float*)d_out;                 // [8,256,256] = [b][s][t]

    (void)in_sizes; (void)n_in; (void)out_size;

    cudaFuncSetAttribute(attn_kernel,
                         cudaFuncAttributeMaxDynamicSharedMemorySize,
                         SMEM_B2_BYTES);

    dim3 gGemm(LDIM / 64, (B_ * TGT) / 128, 2);  // (4, 16, 2) = 128 blocks
    gemm_kernel<<<gGemm, 256>>>(dec, enc, W1, W2);

    dim3 gAttn(TGT / 2, B_);                     // (128, 8) = 1024 blocks
    attn_kernel<<<gAttn, 512, SMEM_B2_BYTES>>>(len, vt, out);
}